// round 15
// baseline (speedup 1.0000x reference)
#include <cuda_runtime.h>
#include <cuda_bf16.h>
#include <cstdint>

#define THREADS 1024
#define NSM     148
#define NITEM   512              // 256 rows * 2 prefix-halves

// Scratch (__device__ globals = allowed)
__device__ int    g_len[256];
__device__ int    g_order[NITEM];     // packed (row<<1)|half, LPT-desc order
__device__ double g_part[NITEM * 6];
__device__ unsigned int g_work = 0;
__device__ unsigned int g_ctr  = 0;

// ---------------- Kernel A: per-row prefix length (one warp per row) ----------------
__global__ void __launch_bounds__(1024)
len_kernel(const int* __restrict__ mask, int T)
{
    const int warp = threadIdx.x >> 5;
    const int lane = threadIdx.x & 31;
    const int row  = blockIdx.x * 32 + warp;
    const int* __restrict__ m = mask + (size_t)row * (size_t)T;

    int lo = T >> 2, hi = T;     // L >= T/4 guaranteed by problem construction
    while (hi - lo > 32) {
        int range = hi - lo;
        int pos = lo + (int)((long long)range * (lane + 1) / 33);
        int v = __ldg(&m[pos]);
        unsigned bal = __ballot_sync(0xffffffffu, v != 0);
        int c = __popc(bal);                 // prefix mask -> contiguous low bits
        int nlo = (c == 0)  ? lo : lo + (int)((long long)range * c / 33);
        int nhi = (c == 32) ? hi : lo + (int)((long long)range * (c + 1) / 33);
        lo = nlo; hi = nhi;
    }
    int pos = lo + lane;
    int v = (pos < hi) ? __ldg(&m[pos]) : 0;
    unsigned bal = __ballot_sync(0xffffffffu, v != 0);
    if (lane == 0) g_len[row] = lo + __popc(bal);
}

// ---------------- Kernel B: LPT schedule (bitonic sort rows by length desc) ----------
__global__ void __launch_bounds__(256)
sched_kernel()
{
    __shared__ int skey[256];
    __shared__ int sval[256];
    const int tid = threadIdx.x;
    skey[tid] = g_len[tid];
    sval[tid] = tid;
    __syncthreads();

    // bitonic sort, descending by key (deterministic network)
    for (int k = 2; k <= 256; k <<= 1) {
        for (int j = k >> 1; j > 0; j >>= 1) {
            int ixj = tid ^ j;
            if (ixj > tid) {
                bool descBlock = ((tid & k) == 0);
                int k0 = skey[tid], k1 = skey[ixj];
                int v0 = sval[tid], v1 = sval[ixj];
                bool swap = descBlock ? (k0 < k1) : (k0 > k1);
                if (swap) {
                    skey[tid] = k1; skey[ixj] = k0;
                    sval[tid] = v1; sval[ixj] = v0;
                }
            }
            __syncthreads();
        }
    }
    // emit both halves of each row, longest rows first
    g_order[2 * tid]     = (sval[tid] << 1);
    g_order[2 * tid + 1] = (sval[tid] << 1) | 1;
}

// ---------------- Kernel C: persistent LPT-scheduled streaming ----------------------
__global__ void __launch_bounds__(THREADS, 1)
ccc_lpt_kernel(const float* __restrict__ yt,
               const float* __restrict__ yp,
               int T, int B,
               float* __restrict__ out)
{
    const int tid  = threadIdx.x;
    const int lane = tid & 31;
    const int warp = tid >> 5;

    __shared__ int sItem;
    __shared__ int sIsLast;
    __shared__ double sred[5][THREADS / 32];

    for (;;) {
        if (tid == 0) sItem = (int)atomicAdd(&g_work, 1);
        __syncthreads();
        const int it = sItem;
        if (it >= NITEM) break;

        const int packed = __ldg(&g_order[it]);
        const int row  = packed >> 1;
        const int half = packed & 1;
        const int L    = __ldg(&g_len[row]);
        const size_t base = (size_t)row * (size_t)T;

        const int split = (L >> 1) & ~3;          // 16B-aligned split of valid prefix
        const int begin = half ? split : 0;
        const int end   = half ? L     : split;
        const int n     = end - begin;

        const float* __restrict__ at = yt + base;
        const float* __restrict__ bt = yp + base;
        const float4* __restrict__ a4 = reinterpret_cast<const float4*>(at);
        const float4* __restrict__ b4 = reinterpret_cast<const float4*>(bt);

        const int i0  = begin >> 2;
        const int i1  = i0 + (n >> 2);
        const int rem = half ? (L & 3) : 0;

        float St = 0.f, Sp = 0.f, Stt = 0.f, Spp = 0.f, Stp = 0.f;

        // R2-proven streaming loop: unroll 4, strided, immediate consume
        #pragma unroll 4
        for (int i = i0 + tid; i < i1; i += THREADS) {
            float4 a = a4[i];
            float4 b = b4[i];
            St  += (a.x + a.y) + (a.z + a.w);
            Sp  += (b.x + b.y) + (b.z + b.w);
            Stt += (a.x * a.x + a.y * a.y) + (a.z * a.z + a.w * a.w);
            Spp += (b.x * b.x + b.y * b.y) + (b.z * b.z + b.w * b.w);
            Stp += (a.x * b.x + a.y * b.y) + (a.z * b.z + a.w * b.w);
        }
        if (tid == 0 && rem) {
            for (int j = i1 * 4; j < i1 * 4 + rem; ++j) {
                float a = at[j], b = bt[j];
                St += a; Sp += b; Stt += a * a; Spp += b * b; Stp += a * b;
            }
        }

        // ---- block reduce (f32 in-warp, double across warps) ----
        #pragma unroll
        for (int o = 16; o; o >>= 1) {
            St  += __shfl_xor_sync(0xffffffffu, St,  o);
            Sp  += __shfl_xor_sync(0xffffffffu, Sp,  o);
            Stt += __shfl_xor_sync(0xffffffffu, Stt, o);
            Spp += __shfl_xor_sync(0xffffffffu, Spp, o);
            Stp += __shfl_xor_sync(0xffffffffu, Stp, o);
        }
        if (lane == 0) {
            sred[0][warp] = (double)St;
            sred[1][warp] = (double)Sp;
            sred[2][warp] = (double)Stt;
            sred[3][warp] = (double)Spp;
            sred[4][warp] = (double)Stp;
        }
        __syncthreads();

        if (tid == 0) {
            double d1 = 0, d2 = 0, d3 = 0, d4 = 0, d5 = 0;
            #pragma unroll
            for (int w = 0; w < THREADS / 32; ++w) {
                d1 += sred[0][w]; d2 += sred[1][w]; d3 += sred[2][w];
                d4 += sred[3][w]; d5 += sred[4][w];
            }
            double* p = g_part + (size_t)packed * 6;   // fixed slot per (row,half)
            p[0] = (double)(n + rem);
            p[1] = d1; p[2] = d2; p[3] = d3; p[4] = d4; p[5] = d5;
        }
        __syncthreads();   // smem (sItem, sred) reuse safety
    }

    // ---- completion counting ----
    if (tid == 0) {
        __threadfence();
        unsigned int c = atomicAdd(&g_ctr, 1);
        sIsLast = (c == (unsigned int)(gridDim.x - 1));
    }
    __syncthreads();

    // ---- last finishing block: combine in fixed order (deterministic) ----
    if (sIsLast) {
        double ccc = 0.0;
        if (tid < B) {
            const double* p = g_part + (size_t)tid * 2 * 6;   // slots (row,0),(row,1)
            double dL   = __ldcg(p + 0) + __ldcg(p + 6);
            double dSt  = __ldcg(p + 1) + __ldcg(p + 7);
            double dSp  = __ldcg(p + 2) + __ldcg(p + 8);
            double dStt = __ldcg(p + 3) + __ldcg(p + 9);
            double dSpp = __ldcg(p + 4) + __ldcg(p + 10);
            double dStp = __ldcg(p + 5) + __ldcg(p + 11);
            double invL = 1.0 / dL;
            double invD = 1.0 / (dL - 1.0);
            double mt_  = dSt * invL;
            double mp_  = dSp * invL;
            double vt   = (dStt - dSt * dSt * invL) * invD;
            double vp   = (dSpp - dSp * dSp * invL) * invD;
            double cov  = (dStp - dSt * dSp * invL) * invD;
            // faithful to reference: (mean_t - mean_p) * 2, NOT squared
            ccc = 2.0 * cov / (vt + vp + (mt_ - mp_) * 2.0);
        }
        #pragma unroll
        for (int o = 16; o; o >>= 1)
            ccc += __shfl_xor_sync(0xffffffffu, ccc, o);
        __shared__ double sfin[THREADS / 32];
        if (lane == 0) sfin[warp] = ccc;
        __syncthreads();
        if (tid < 32) {
            double t2 = (tid < THREADS / 32) ? sfin[tid] : 0.0;
            #pragma unroll
            for (int o = 16; o; o >>= 1)
                t2 += __shfl_xor_sync(0xffffffffu, t2, o);
            if (tid == 0) {
                out[0] = (float)(t2 / (double)B);
                g_ctr  = 0;   // re-arm for next graph replay
                g_work = 0;
            }
        }
    }
}

extern "C" void kernel_launch(void* const* d_in, const int* in_sizes, int n_in,
                              void* d_out, int out_size)
{
    const float* yt  = (const float*)d_in[0];
    const float* yp  = (const float*)d_in[1];
    const int*   msk = (const int*)d_in[2];

    const int B = 256;                 // fixed problem shape
    const int T = in_sizes[0] / B;     // 65536

    len_kernel<<<B / 32, 1024>>>(msk, T);
    sched_kernel<<<1, 256>>>();
    ccc_lpt_kernel<<<NSM, THREADS>>>(yt, yp, T, B, (float*)d_out);
}

// round 16
// speedup vs baseline: 2.1203x; 2.1203x over previous
#include <cuda_runtime.h>
#include <cuda_bf16.h>
#include <cstdint>

#define THREADS 256
#define STAGE   1792             // TMA stage elements (7168 B)
#define RING    3
#define NBLK    512              // 256 rows * {LDG-lower, TMA-upper}

__device__ double g_part[NBLK * 6];
__device__ unsigned int g_ctr = 0;

__device__ __forceinline__ void mbar_init(unsigned int mb, unsigned int cnt) {
    asm volatile("mbarrier.init.shared.b64 [%0], %1;" :: "r"(mb), "r"(cnt) : "memory");
}
__device__ __forceinline__ void mbar_expect_tx(unsigned int mb, unsigned int bytes) {
    asm volatile("mbarrier.arrive.expect_tx.shared.b64 _, [%0], %1;"
                 :: "r"(mb), "r"(bytes) : "memory");
}
__device__ __forceinline__ void bulk_g2s(unsigned int dst, const void* src,
                                         unsigned int bytes, unsigned int mb) {
    asm volatile(
        "cp.async.bulk.shared::cta.global.mbarrier::complete_tx::bytes [%0], [%1], %2, [%3];"
        :: "r"(dst), "l"(src), "r"(bytes), "r"(mb) : "memory");
}
__device__ __forceinline__ void mbar_wait(unsigned int mb, unsigned int parity) {
    asm volatile(
        "{\n\t"
        ".reg .pred P;\n\t"
        "WAIT_%=:\n\t"
        "mbarrier.try_wait.parity.acquire.cta.shared::cta.b64 P, [%0], %1, 0x989680;\n\t"
        "@P bra.uni DONE_%=;\n\t"
        "bra.uni WAIT_%=;\n\t"
        "DONE_%=:\n\t"
        "}"
        :: "r"(mb), "r"(parity) : "memory");
}

__global__ void __launch_bounds__(THREADS)
ccc_dual_kernel(const float* __restrict__ yt,
                const float* __restrict__ yp,
                const int*   __restrict__ mask,
                int T, int B,
                float* __restrict__ out)
{
    const int bid  = blockIdx.x;
    const int row  = bid >> 1;
    const int kind = bid & 1;            // 0 = LDG lower half, 1 = TMA upper half
    const size_t base = (size_t)row * (size_t)T;

    const int tid  = threadIdx.x;
    const int lane = tid & 31;
    const int warp = tid >> 5;

    __shared__ __align__(16) float sA[RING][STAGE];
    __shared__ __align__(16) float sB[RING][STAGE];
    __shared__ __align__(8)  unsigned long long smbar[RING];
    __shared__ int sL;
    __shared__ int sIsLast;
    __shared__ double sred[5][THREADS / 32];

    // ---- warp 0: 32-ary prefix search on [T/4, T] (L >= T/4 guaranteed) ----
    if (tid < 32) {
        const int* __restrict__ m = mask + base;
        int lo = T >> 2, hi = T;
        while (hi - lo > 32) {
            int range = hi - lo;
            int pos = lo + (int)((long long)range * (lane + 1) / 33);
            int v = __ldg(&m[pos]);
            unsigned bal = __ballot_sync(0xffffffffu, v != 0);
            int c = __popc(bal);
            int nlo = (c == 0)  ? lo : lo + (int)((long long)range * c / 33);
            int nhi = (c == 32) ? hi : lo + (int)((long long)range * (c + 1) / 33);
            lo = nlo; hi = nhi;
        }
        int pos = lo + lane;
        int v = (pos < hi) ? __ldg(&m[pos]) : 0;
        unsigned bal = __ballot_sync(0xffffffffu, v != 0);
        if (lane == 0) sL = lo + __popc(bal);
    }
    __syncthreads();
    const int L = sL;
    const int split = (L >> 1) & ~3;     // 16B-aligned split of valid prefix

    float St = 0.f, Sp = 0.f, Stt = 0.f, Spp = 0.f, Stp = 0.f;
    int count = 0;

    if (kind == 0) {
        // ================= LDG path: lower half [0, split) =================
        const float4* __restrict__ a4 = reinterpret_cast<const float4*>(yt + base);
        const float4* __restrict__ b4 = reinterpret_cast<const float4*>(yp + base);
        const int i1 = split >> 2;
        count = split;

        #pragma unroll 4
        for (int i = tid; i < i1; i += THREADS) {
            float4 a = a4[i];
            float4 b = b4[i];
            St  += (a.x + a.y) + (a.z + a.w);
            Sp  += (b.x + b.y) + (b.z + b.w);
            Stt += (a.x * a.x + a.y * a.y) + (a.z * a.z + a.w * a.w);
            Spp += (b.x * b.x + b.y * b.y) + (b.z * b.z + b.w * b.w);
            Stp += (a.x * b.x + a.y * b.y) + (a.z * b.z + a.w * b.w);
        }
    } else {
        // ================= TMA path: upper half [split, L) =================
        const int n = L - split;                 // >= T/8 > 0 always
        count = n;
        const float* __restrict__ at = yt + base + split;
        const float* __restrict__ bt = yp + base + split;
        const int nst = (n + STAGE - 1) / STAGE;

        unsigned int mb[RING], dA[RING], dB[RING];
        #pragma unroll
        for (int r = 0; r < RING; ++r) {
            mb[r] = (unsigned int)__cvta_generic_to_shared(&smbar[r]);
            dA[r] = (unsigned int)__cvta_generic_to_shared(&sA[r][0]);
            dB[r] = (unsigned int)__cvta_generic_to_shared(&sB[r][0]);
        }
        if (tid == 0) {
            #pragma unroll
            for (int r = 0; r < RING; ++r) mbar_init(mb[r], 1);
        }
        __syncthreads();

        if (tid == 0) {
            #pragma unroll
            for (int r = 0; r < RING; ++r) {
                if (r < nst) {
                    int v = n - r * STAGE; v = (v > STAGE) ? STAGE : v;
                    unsigned int bytes = ((unsigned int)(v * 4) + 15u) & ~15u;
                    mbar_expect_tx(mb[r], 2u * bytes);
                    bulk_g2s(dA[r], at + r * STAGE, bytes, mb[r]);
                    bulk_g2s(dB[r], bt + r * STAGE, bytes, mb[r]);
                }
            }
        }

        int slot = 0, parity = 0;
        for (int s = 0; s < nst; ++s) {
            mbar_wait(mb[slot], parity);

            int v = n - s * STAGE; v = (v > STAGE) ? STAGE : v;
            const int v4 = v >> 2;
            const float4* __restrict__ a4 = reinterpret_cast<const float4*>(&sA[slot][0]);
            const float4* __restrict__ b4 = reinterpret_cast<const float4*>(&sB[slot][0]);

            #pragma unroll 4
            for (int i = tid; i < v4; i += THREADS) {
                float4 a = a4[i];
                float4 b = b4[i];
                St  += (a.x + a.y) + (a.z + a.w);
                Sp  += (b.x + b.y) + (b.z + b.w);
                Stt += (a.x * a.x + a.y * a.y) + (a.z * a.z + a.w * a.w);
                Spp += (b.x * b.x + b.y * b.y) + (b.z * b.z + b.w * b.w);
                Stp += (a.x * b.x + a.y * b.y) + (a.z * b.z + a.w * b.w);
            }
            if (tid == 0 && (v & 3)) {
                for (int j = v4 * 4; j < v; ++j) {
                    float a = sA[slot][j], b = sB[slot][j];
                    St += a; Sp += b; Stt += a * a; Spp += b * b; Stp += a * b;
                }
            }
            __syncthreads();

            const int ns = s + RING;
            if (tid == 0 && ns < nst) {
                int vv = n - ns * STAGE; vv = (vv > STAGE) ? STAGE : vv;
                unsigned int bytes = ((unsigned int)(vv * 4) + 15u) & ~15u;
                mbar_expect_tx(mb[slot], 2u * bytes);
                bulk_g2s(dA[slot], at + ns * STAGE, bytes, mb[slot]);
                bulk_g2s(dB[slot], bt + ns * STAGE, bytes, mb[slot]);
            }
            if (++slot == RING) { slot = 0; parity ^= 1; }
        }
    }

    // ---- block reduce (f32 in-warp, double across warps) ----
    #pragma unroll
    for (int o = 16; o; o >>= 1) {
        St  += __shfl_xor_sync(0xffffffffu, St,  o);
        Sp  += __shfl_xor_sync(0xffffffffu, Sp,  o);
        Stt += __shfl_xor_sync(0xffffffffu, Stt, o);
        Spp += __shfl_xor_sync(0xffffffffu, Spp, o);
        Stp += __shfl_xor_sync(0xffffffffu, Stp, o);
    }
    if (lane == 0) {
        sred[0][warp] = (double)St;
        sred[1][warp] = (double)Sp;
        sred[2][warp] = (double)Stt;
        sred[3][warp] = (double)Spp;
        sred[4][warp] = (double)Stp;
    }
    __syncthreads();

    if (tid == 0) {
        double d1 = 0, d2 = 0, d3 = 0, d4 = 0, d5 = 0;
        #pragma unroll
        for (int w = 0; w < THREADS / 32; ++w) {
            d1 += sred[0][w]; d2 += sred[1][w]; d3 += sred[2][w];
            d4 += sred[3][w]; d5 += sred[4][w];
        }
        double* p = g_part + (size_t)bid * 6;
        p[0] = (double)count;
        p[1] = d1; p[2] = d2; p[3] = d3; p[4] = d4; p[5] = d5;
        __threadfence();
        unsigned int c = atomicAdd(&g_ctr, 1);
        sIsLast = (c == (unsigned int)(gridDim.x - 1));
    }
    __syncthreads();

    // ---- last finishing block: combine in fixed order (deterministic) ----
    if (sIsLast) {
        double ccc = 0.0;
        if (tid < B) {
            const double* p = g_part + (size_t)tid * 2 * 6;
            double dL   = __ldcg(p + 0) + __ldcg(p + 6);
            double dSt  = __ldcg(p + 1) + __ldcg(p + 7);
            double dSp  = __ldcg(p + 2) + __ldcg(p + 8);
            double dStt = __ldcg(p + 3) + __ldcg(p + 9);
            double dSpp = __ldcg(p + 4) + __ldcg(p + 10);
            double dStp = __ldcg(p + 5) + __ldcg(p + 11);
            double invL = 1.0 / dL;
            double invD = 1.0 / (dL - 1.0);
            double mt_  = dSt * invL;
            double mp_  = dSp * invL;
            double vt   = (dStt - dSt * dSt * invL) * invD;
            double vp   = (dSpp - dSp * dSp * invL) * invD;
            double cov  = (dStp - dSt * dSp * invL) * invD;
            // faithful to reference: (mean_t - mean_p) * 2, NOT squared
            ccc = 2.0 * cov / (vt + vp + (mt_ - mp_) * 2.0);
        }
        #pragma unroll
        for (int o = 16; o; o >>= 1)
            ccc += __shfl_xor_sync(0xffffffffu, ccc, o);
        __shared__ double sfin[THREADS / 32];
        if (lane == 0) sfin[warp] = ccc;
        __syncthreads();
        if (tid < 32) {
            double t2 = (tid < THREADS / 32) ? sfin[tid] : 0.0;
            #pragma unroll
            for (int o = 4; o; o >>= 1)
                t2 += __shfl_xor_sync(0xffffffffu, t2, o);
            if (tid == 0) {
                out[0] = (float)(t2 / (double)B);
                g_ctr = 0;   // re-arm for next graph replay
            }
        }
    }
}

extern "C" void kernel_launch(void* const* d_in, const int* in_sizes, int n_in,
                              void* d_out, int out_size)
{
    const float* yt  = (const float*)d_in[0];
    const float* yp  = (const float*)d_in[1];
    const int*   msk = (const int*)d_in[2];

    const int B = 256;                 // fixed problem shape
    const int T = in_sizes[0] / B;     // 65536

    ccc_dual_kernel<<<NBLK, THREADS>>>(yt, yp, msk, T, B, (float*)d_out);
}